// round 2
// baseline (speedup 1.0000x reference)
#include <cuda_runtime.h>
#include <cuda_bf16.h>
#include <math.h>

#define B 4096
#define D 256
#define MARGIN 0.3f

// Scratch (device globals — no allocation allowed)
__device__ float g_d2[(size_t)B * B];   // stores dist (sqrt applied)
__device__ float g_sq[B];
__device__ float g_hp[B];
__device__ float g_hn[B];
__device__ int   g_lab[B];              // normalized int32 labels

// ---------------------------------------------------------------------------
// Kernel L: normalize labels. Detect int64-vs-int32 on device:
// if int64 (values in [0,64)), all odd 32-bit words are 0.
// if int32 random labels, odd words are random in [0,64) -> virtually surely nonzero somewhere.
// ---------------------------------------------------------------------------
__global__ __launch_bounds__(1024) void k_labels(const int* __restrict__ raw) {
    __shared__ int s_any_nonzero;
    const int tid = threadIdx.x;
    if (tid == 0) s_any_nonzero = 0;
    __syncthreads();

    int local = 0;
    // Check odd words under the int64 interpretation: raw[2i+1], i in [0,B)
    for (int i = tid; i < B; i += 1024) {
        if (raw[2 * i + 1] != 0) local = 1;
    }
    if (local) atomicOr(&s_any_nonzero, 1);
    __syncthreads();

    const bool is_i32 = (s_any_nonzero != 0);
    for (int i = tid; i < B; i += 1024) {
        g_lab[i] = is_i32 ? raw[i] : raw[2 * i];
    }
}

// ---------------------------------------------------------------------------
// Kernel 0: row squared norms. One warp per row.
// ---------------------------------------------------------------------------
__global__ void k_sq(const float* __restrict__ E) {
    int row = blockIdx.x * blockDim.y + threadIdx.y;
    int lane = threadIdx.x;
    if (row >= B) return;
    float s = 0.f;
    const float* e = E + (size_t)row * D;
    #pragma unroll
    for (int d = lane; d < D; d += 32) {
        float v = e[d];
        s += v * v;
    }
    #pragma unroll
    for (int off = 16; off > 0; off >>= 1)
        s += __shfl_xor_sync(0xFFFFFFFFu, s, off);
    if (lane == 0) g_sq[row] = s;
}

// ---------------------------------------------------------------------------
// Kernel 1: pairwise distances, 64x64 tile per block, 4x4 per thread.
// ---------------------------------------------------------------------------
__global__ __launch_bounds__(256) void k_dist(const float* __restrict__ E) {
    __shared__ float As[64][33];
    __shared__ float Bs[64][33];

    const int bi = blockIdx.y * 64;
    const int bj = blockIdx.x * 64;
    const int tx = threadIdx.x;   // 0..15
    const int ty = threadIdx.y;   // 0..15
    const int tid = ty * 16 + tx;

    float acc[4][4];
    #pragma unroll
    for (int r = 0; r < 4; r++)
        #pragma unroll
        for (int c = 0; c < 4; c++)
            acc[r][c] = 0.f;

    for (int k0 = 0; k0 < D; k0 += 32) {
        #pragma unroll
        for (int idx = tid; idx < 64 * 32; idx += 256) {
            int r = idx >> 5;
            int c = idx & 31;
            As[r][c] = E[(size_t)(bi + r) * D + k0 + c];
            Bs[r][c] = E[(size_t)(bj + r) * D + k0 + c];
        }
        __syncthreads();

        #pragma unroll
        for (int k = 0; k < 32; k++) {
            float a[4], b[4];
            #pragma unroll
            for (int r = 0; r < 4; r++) a[r] = As[ty * 4 + r][k];
            #pragma unroll
            for (int c = 0; c < 4; c++) b[c] = Bs[tx * 4 + c][k];
            #pragma unroll
            for (int r = 0; r < 4; r++)
                #pragma unroll
                for (int c = 0; c < 4; c++)
                    acc[r][c] = fmaf(a[r], b[c], acc[r][c]);
        }
        __syncthreads();
    }

    #pragma unroll
    for (int r = 0; r < 4; r++) {
        int i = bi + ty * 4 + r;
        float sqi = g_sq[i];
        #pragma unroll
        for (int c = 0; c < 4; c++) {
            int j = bj + tx * 4 + c;
            float d2 = sqi + g_sq[j] - 2.f * acc[r][c];
            g_d2[(size_t)i * B + j] = sqrtf(fmaxf(d2, 0.f));
        }
    }
}

// ---------------------------------------------------------------------------
// Kernel 2: per-row hard positive / hard negative. One block per row.
// ---------------------------------------------------------------------------
__global__ __launch_bounds__(256) void k_row() {
    const int i = blockIdx.x;
    const int tid = threadIdx.x;
    const int li = g_lab[i];

    float hp = -1e30f;
    float hn = 1e30f;
    const float* row = g_d2 + (size_t)i * B;
    for (int j = tid; j < B; j += 256) {
        float d = row[j];
        bool same = (g_lab[j] == li);
        if (same) {
            if (j != i) hp = fmaxf(hp, d);
        } else {
            hn = fminf(hn, d);
        }
    }

    __shared__ float shp[256];
    __shared__ float shn[256];
    shp[tid] = hp;
    shn[tid] = hn;
    __syncthreads();
    #pragma unroll
    for (int off = 128; off > 0; off >>= 1) {
        if (tid < off) {
            shp[tid] = fmaxf(shp[tid], shp[tid + off]);
            shn[tid] = fminf(shn[tid], shn[tid + off]);
        }
        __syncthreads();
    }
    if (tid == 0) {
        g_hp[i] = shp[0];
        g_hn[i] = shn[0];
    }
}

// ---------------------------------------------------------------------------
// Kernel 3: final mean over valid rows. Single block.
// ---------------------------------------------------------------------------
__global__ __launch_bounds__(1024) void k_final(float* __restrict__ out) {
    const int tid = threadIdx.x;
    float sum = 0.f;
    float cnt = 0.f;
    for (int i = tid; i < B; i += 1024) {
        float hp = g_hp[i];
        float hn = g_hn[i];
        if (hp > -1e29f && hn < 1e29f) {
            float l = hp - hn + MARGIN;
            if (l > 0.f) sum += l;
            cnt += 1.f;
        }
    }
    __shared__ float ssum[1024];
    __shared__ float scnt[1024];
    ssum[tid] = sum;
    scnt[tid] = cnt;
    __syncthreads();
    #pragma unroll
    for (int off = 512; off > 0; off >>= 1) {
        if (tid < off) {
            ssum[tid] += ssum[tid + off];
            scnt[tid] += scnt[tid + off];
        }
        __syncthreads();
    }
    if (tid == 0) {
        float c = scnt[0];
        out[0] = (c > 0.f) ? (ssum[0] / c) : 0.f;
    }
}

// ---------------------------------------------------------------------------
extern "C" void kernel_launch(void* const* d_in, const int* in_sizes, int n_in,
                              void* d_out, int out_size) {
    const float* E = (const float*)d_in[0];
    const int* labels_raw = (const int*)d_in[1];
    float* out = (float*)d_out;

    k_labels<<<1, 1024>>>(labels_raw);
    {
        dim3 blk(32, 8);
        dim3 grd((B + 7) / 8);
        k_sq<<<grd, blk>>>(E);
    }
    {
        dim3 blk(16, 16);
        dim3 grd(B / 64, B / 64);
        k_dist<<<grd, blk>>>(E);
    }
    k_row<<<B, 256>>>();
    k_final<<<1, 1024>>>(out);
}

// round 3
// speedup vs baseline: 1.7544x; 1.7544x over previous
#include <cuda_runtime.h>
#include <math.h>

#define B 4096
#define D 256
#define MARGIN 0.3f
#define BM 128
#define BN 128
#define BK 16
#define CHUNK_COLS 512

// Device scratch (no allocations allowed)
__device__ int   g_hp_bits[B];   // max d2 over positives (nonneg-float bits, atomicMax int)
__device__ int   g_hn_bits[B];   // min d2 over negatives
__device__ float g_sq[B];
__device__ int   g_lab[B];
__device__ int   g_cnt[64];

// ---------------------------------------------------------------------------
// f32x2 helpers (Blackwell packed fp32)
// ---------------------------------------------------------------------------
__device__ __forceinline__ void fma2(unsigned long long& d, unsigned long long a,
                                     unsigned long long b) {
    asm("fma.rn.f32x2 %0, %1, %2, %3;" : "=l"(d) : "l"(a), "l"(b), "l"(d));
}
__device__ __forceinline__ unsigned long long pack2(float x, float y) {
    unsigned long long r;
    asm("mov.b64 %0, {%1, %2};" : "=l"(r) : "f"(x), "f"(y));
    return r;
}
__device__ __forceinline__ float2 unpack2(unsigned long long v) {
    float2 r;
    asm("mov.b64 {%0, %1}, %2;" : "=f"(r.x), "=f"(r.y) : "l"(v));
    return r;
}

// ---------------------------------------------------------------------------
// Kernel L: normalize labels (int64-vs-int32 detect), histogram, init reductions.
// ---------------------------------------------------------------------------
__global__ __launch_bounds__(1024) void k_labels(const int* __restrict__ raw) {
    __shared__ int s_any;
    __shared__ int s_hist[64];
    const int tid = threadIdx.x;
    if (tid == 0) s_any = 0;
    if (tid < 64) s_hist[tid] = 0;
    __syncthreads();

    int local = 0;
    for (int i = tid; i < B; i += 1024)
        if (raw[2 * i + 1] != 0) local = 1;
    if (local) atomicOr(&s_any, 1);
    __syncthreads();

    const bool is_i32 = (s_any != 0);
    for (int i = tid; i < B; i += 1024) {
        int l = is_i32 ? raw[i] : raw[2 * i];
        g_lab[i] = l;
        atomicAdd(&s_hist[l & 63], 1);
        g_hp_bits[i] = 0;            // 0.0f
        g_hn_bits[i] = 0x7F7FFFFF;   // FLT_MAX
    }
    __syncthreads();
    if (tid < 64) g_cnt[tid] = s_hist[tid];
}

// ---------------------------------------------------------------------------
// Kernel 0: row squared norms. One warp per row.
// ---------------------------------------------------------------------------
__global__ void k_sq(const float* __restrict__ E) {
    int row = blockIdx.x * blockDim.y + threadIdx.y;
    int lane = threadIdx.x;
    if (row >= B) return;
    float s = 0.f;
    const float4* e = (const float4*)(E + (size_t)row * D);
    #pragma unroll
    for (int d = lane; d < D / 4; d += 32) {
        float4 v = e[d];
        s += v.x * v.x + v.y * v.y + v.z * v.z + v.w * v.w;
    }
    #pragma unroll
    for (int off = 16; off > 0; off >>= 1)
        s += __shfl_xor_sync(0xFFFFFFFFu, s, off);
    if (lane == 0) g_sq[row] = s;
}

// ---------------------------------------------------------------------------
// Fused distance + hard-pos/neg reduction.
// Grid: (B/CHUNK_COLS, B/BM) = (8, 32). Block: 256 threads (16x16 logical).
// Each block: 128-row strip x 512-col chunk (4 j-tiles of 128).
// Reduction in d2-space; sqrt deferred to k_final.
// ---------------------------------------------------------------------------
__global__ __launch_bounds__(256, 2) void k_fused(const float* __restrict__ E) {
    __shared__ float As[BK][BM + 4];   // transposed, stride 132
    __shared__ float Bs[BK][BN + 4];

    const int tid = threadIdx.x;
    const int tx = tid & 15;
    const int ty = tid >> 4;
    const int i0 = blockIdx.y * BM;
    const int c0 = blockIdx.x * CHUNK_COLS;

    float hp[8], hn[8];
    #pragma unroll
    for (int r = 0; r < 8; r++) { hp[r] = 0.f; hn[r] = 3.4e38f; }

    for (int jt = 0; jt < 4; jt++) {
        const int j0 = c0 + jt * BN;

        unsigned long long acc[8][4];
        #pragma unroll
        for (int r = 0; r < 8; r++)
            #pragma unroll
            for (int c = 0; c < 4; c++)
                acc[r][c] = 0ull;

        for (int k0 = 0; k0 < D; k0 += BK) {
            // Load 128x16 tiles of A and B, transposed into smem.
            #pragma unroll
            for (int it = 0; it < 2; it++) {
                int f = tid + it * 256;        // 0..511 float4 slots
                int row = f >> 2;
                int q = f & 3;
                float4 va = *(const float4*)&E[(size_t)(i0 + row) * D + k0 + 4 * q];
                float4 vb = *(const float4*)&E[(size_t)(j0 + row) * D + k0 + 4 * q];
                As[4 * q + 0][row] = va.x; As[4 * q + 1][row] = va.y;
                As[4 * q + 2][row] = va.z; As[4 * q + 3][row] = va.w;
                Bs[4 * q + 0][row] = vb.x; Bs[4 * q + 1][row] = vb.y;
                Bs[4 * q + 2][row] = vb.z; Bs[4 * q + 3][row] = vb.w;
            }
            __syncthreads();

            #pragma unroll
            for (int k = 0; k < BK; k++) {
                float4 b0 = *(const float4*)&Bs[k][tx * 8];
                float4 b1 = *(const float4*)&Bs[k][tx * 8 + 4];
                unsigned long long b2[4];
                b2[0] = pack2(b0.x, b0.y); b2[1] = pack2(b0.z, b0.w);
                b2[2] = pack2(b1.x, b1.y); b2[3] = pack2(b1.z, b1.w);
                float4 a0 = *(const float4*)&As[k][ty * 8];
                float4 a1 = *(const float4*)&As[k][ty * 8 + 4];
                float av[8] = {a0.x, a0.y, a0.z, a0.w, a1.x, a1.y, a1.z, a1.w};
                #pragma unroll
                for (int r = 0; r < 8; r++) {
                    unsigned long long a2 = pack2(av[r], av[r]);
                    #pragma unroll
                    for (int c = 0; c < 4; c++)
                        fma2(acc[r][c], a2, b2[c]);
                }
            }
            __syncthreads();
        }

        // Epilogue: d2 + masked hard-pos/neg update (d2-space).
        int lj[8]; float sqj[8];
        #pragma unroll
        for (int c = 0; c < 8; c++) {
            lj[c] = g_lab[j0 + tx * 8 + c];
            sqj[c] = g_sq[j0 + tx * 8 + c];
        }
        #pragma unroll
        for (int r = 0; r < 8; r++) {
            const int gi = i0 + ty * 8 + r;
            const int li = g_lab[gi];
            const float sqi = g_sq[gi];
            #pragma unroll
            for (int c2 = 0; c2 < 4; c2++) {
                float2 dd = unpack2(acc[r][c2]);
                float dotv[2] = {dd.x, dd.y};
                #pragma unroll
                for (int h = 0; h < 2; h++) {
                    const int c = 2 * c2 + h;
                    const int gj = j0 + tx * 8 + c;
                    float d2 = fmaf(-2.f, dotv[h], sqi + sqj[c]);
                    if (lj[c] == li) {
                        if (gi != gj) hp[r] = fmaxf(hp[r], d2);
                    } else {
                        hn[r] = fminf(hn[r], d2);
                    }
                }
            }
        }
    }

    // Reduce across tx (lane bits 0..3), then atomics on float-bit ints.
    #pragma unroll
    for (int r = 0; r < 8; r++) {
        float vp = hp[r], vn = hn[r];
        #pragma unroll
        for (int m = 1; m < 16; m <<= 1) {
            vp = fmaxf(vp, __shfl_xor_sync(0xFFFFFFFFu, vp, m));
            vn = fminf(vn, __shfl_xor_sync(0xFFFFFFFFu, vn, m));
        }
        if (tx == 0) {
            const int row = i0 + ty * 8 + r;
            atomicMax(&g_hp_bits[row], __float_as_int(vp));
            atomicMin(&g_hn_bits[row], __float_as_int(vn));
        }
    }
}

// ---------------------------------------------------------------------------
// Final: loss_i = relu(sqrt(hp_d2) - sqrt(hn_d2) + margin) for valid rows; mean.
// Validity from label histogram (pos exists: cnt>=2, neg exists: cnt<B).
// ---------------------------------------------------------------------------
__global__ __launch_bounds__(1024) void k_final(float* __restrict__ out) {
    const int tid = threadIdx.x;
    float sum = 0.f, cnt = 0.f;
    for (int i = tid; i < B; i += 1024) {
        const int c = g_cnt[g_lab[i] & 63];
        const bool valid = (c >= 2) && (c <= B - 1);
        if (valid) {
            float hp = sqrtf(fmaxf(__int_as_float(g_hp_bits[i]), 0.f));
            float hn = sqrtf(fmaxf(__int_as_float(g_hn_bits[i]), 0.f));
            float l = hp - hn + MARGIN;
            if (l > 0.f) sum += l;
            cnt += 1.f;
        }
    }
    __shared__ float ssum[1024];
    __shared__ float scnt[1024];
    ssum[tid] = sum;
    scnt[tid] = cnt;
    __syncthreads();
    #pragma unroll
    for (int off = 512; off > 0; off >>= 1) {
        if (tid < off) {
            ssum[tid] += ssum[tid + off];
            scnt[tid] += scnt[tid + off];
        }
        __syncthreads();
    }
    if (tid == 0) {
        float c = scnt[0];
        out[0] = (c > 0.f) ? (ssum[0] / c) : 0.f;
    }
}

// ---------------------------------------------------------------------------
extern "C" void kernel_launch(void* const* d_in, const int* in_sizes, int n_in,
                              void* d_out, int out_size) {
    const float* E = (const float*)d_in[0];
    const int* labels_raw = (const int*)d_in[1];
    float* out = (float*)d_out;

    k_labels<<<1, 1024>>>(labels_raw);
    {
        dim3 blk(32, 8);
        dim3 grd((B + 7) / 8);
        k_sq<<<grd, blk>>>(E);
    }
    {
        dim3 grd(B / CHUNK_COLS, B / BM);   // (8, 32)
        k_fused<<<grd, 256>>>(E);
    }
    k_final<<<1, 1024>>>(out);
}

// round 5
// speedup vs baseline: 3.4483x; 1.9655x over previous
#include <cuda_runtime.h>
#include <cuda_bf16.h>
#include <math.h>
#include <stdint.h>

#define B 4096
#define D 256
#define MARGIN 0.3f
#define NTHREADS 256
#define BK 32            // bf16 K elems per stage
#define NSTAGE 8         // D / BK
#define STRIDE 80        // smem row stride bytes (64B data + 16B pad -> conflict-free)
#define TILE_BYTES (128 * STRIDE)        // 10240 per matrix
#define STAGE_BYTES (4 * TILE_BYTES)     // Ahi|Alo|Bhi|Blo = 40960
#define SMEM_RED (2 * STAGE_BYTES)       // 81920: s_hp[128], s_hn[128]
#define SMEM_TOTAL (SMEM_RED + 1024)

// ---- device scratch ----
__device__ int   g_hp_bits[B];
__device__ int   g_hn_bits[B];
__device__ float g_sq[B];
__device__ int   g_lab[B];
__device__ int   g_cnt[64];
__device__ __nv_bfloat16 g_Ehi[B * D];
__device__ __nv_bfloat16 g_Elo[B * D];

// ---------------------------------------------------------------------------
// PTX helpers (all sm_80+ / family-safe; no a-only instructions)
// ---------------------------------------------------------------------------
__device__ __forceinline__ void cp16(uint32_t s, const void* g) {
    asm volatile("cp.async.cg.shared.global [%0], [%1], 16;" :: "r"(s), "l"(g));
}
__device__ __forceinline__ void cp_commit() {
    asm volatile("cp.async.commit_group;");
}
template <int N>
__device__ __forceinline__ void cp_wait() {
    asm volatile("cp.async.wait_group %0;" :: "n"(N));
}
__device__ __forceinline__ void ldm4(uint32_t* r, uint32_t addr) {
    asm volatile("ldmatrix.sync.aligned.m8n8.x4.shared.b16 {%0,%1,%2,%3}, [%4];"
                 : "=r"(r[0]), "=r"(r[1]), "=r"(r[2]), "=r"(r[3]) : "r"(addr));
}
__device__ __forceinline__ void mma_bf16(float* c, const uint32_t* a,
                                         uint32_t b0, uint32_t b1) {
    asm volatile(
        "mma.sync.aligned.m16n8k16.row.col.f32.bf16.bf16.f32 "
        "{%0,%1,%2,%3}, {%4,%5,%6,%7}, {%8,%9}, {%0,%1,%2,%3};"
        : "+f"(c[0]), "+f"(c[1]), "+f"(c[2]), "+f"(c[3])
        : "r"(a[0]), "r"(a[1]), "r"(a[2]), "r"(a[3]), "r"(b0), "r"(b1));
}

// ---------------------------------------------------------------------------
// k_labels: dtype detect + normalize + histogram + init reductions
// ---------------------------------------------------------------------------
__global__ __launch_bounds__(1024) void k_labels(const int* __restrict__ raw) {
    __shared__ int s_any;
    __shared__ int s_hist[64];
    const int tid = threadIdx.x;
    if (tid == 0) s_any = 0;
    if (tid < 64) s_hist[tid] = 0;
    __syncthreads();
    int local = 0;
    for (int i = tid; i < B; i += 1024)
        if (raw[2 * i + 1] != 0) local = 1;
    if (local) atomicOr(&s_any, 1);
    __syncthreads();
    const bool is_i32 = (s_any != 0);
    for (int i = tid; i < B; i += 1024) {
        int l = is_i32 ? raw[i] : raw[2 * i];
        g_lab[i] = l;
        atomicAdd(&s_hist[l & 63], 1);
        g_hp_bits[i] = 0;
        g_hn_bits[i] = 0x7F7FFFFF;
    }
    __syncthreads();
    if (tid < 64) g_cnt[tid] = s_hist[tid];
}

// ---------------------------------------------------------------------------
// k_prep: bf16 hi/lo split (elementwise)
// ---------------------------------------------------------------------------
__global__ __launch_bounds__(256) void k_prep(const float* __restrict__ E) {
    int idx = blockIdx.x * 256 + threadIdx.x;
    if (idx < B * D / 4) {
        float4 v = ((const float4*)E)[idx];
        __nv_bfloat16 h0 = __float2bfloat16(v.x);
        __nv_bfloat16 h1 = __float2bfloat16(v.y);
        __nv_bfloat16 h2 = __float2bfloat16(v.z);
        __nv_bfloat16 h3 = __float2bfloat16(v.w);
        __nv_bfloat16 l0 = __float2bfloat16(v.x - __bfloat162float(h0));
        __nv_bfloat16 l1 = __float2bfloat16(v.y - __bfloat162float(h1));
        __nv_bfloat16 l2 = __float2bfloat16(v.z - __bfloat162float(h2));
        __nv_bfloat16 l3 = __float2bfloat16(v.w - __bfloat162float(h3));
        __nv_bfloat162* ph = (__nv_bfloat162*)(g_Ehi + 4 * idx);
        __nv_bfloat162* pl = (__nv_bfloat162*)(g_Elo + 4 * idx);
        ph[0] = __nv_bfloat162(h0, h1);
        ph[1] = __nv_bfloat162(h2, h3);
        pl[0] = __nv_bfloat162(l0, l1);
        pl[1] = __nv_bfloat162(l2, l3);
    }
}

__global__ void k_sq(const float* __restrict__ E) {
    int row = blockIdx.x * blockDim.y + threadIdx.y;
    int lane = threadIdx.x;
    if (row >= B) return;
    float s = 0.f;
    const float4* e = (const float4*)(E + (size_t)row * D);
    #pragma unroll
    for (int d = lane; d < D / 4; d += 32) {
        float4 v = e[d];
        s += v.x * v.x + v.y * v.y + v.z * v.z + v.w * v.w;
    }
    #pragma unroll
    for (int off = 16; off > 0; off >>= 1)
        s += __shfl_xor_sync(0xFFFFFFFFu, s, off);
    if (lane == 0) g_sq[row] = s;
}

// ---------------------------------------------------------------------------
// k_gemm: HMMA bf16 split-3 128x128 tile, cp.async double buffer,
//         fused d2 hard-pos/neg epilogue
// ---------------------------------------------------------------------------
__device__ __forceinline__ void issue_stage(uint32_t sbase, int i0, int j0,
                                            int s, int tid) {
    const int k0 = s * BK;
    #pragma unroll
    for (int m = 0; m < 8; m++) {
        int task = m * NTHREADS + tid;          // 0..2047
        int mat = task >> 9;                    // 0 Ahi, 1 Alo, 2 Bhi, 3 Blo
        int idx = task & 511;
        int row = idx >> 2;
        int q = idx & 3;
        int grow = (mat < 2 ? i0 : j0) + row;
        const __nv_bfloat16* base = (mat & 1) ? g_Elo : g_Ehi;
        const __nv_bfloat16* src = base + (size_t)grow * D + k0 + q * 8;
        uint32_t dst = sbase + mat * TILE_BYTES + row * STRIDE + q * 16;
        cp16(dst, src);
    }
}

__global__ __launch_bounds__(NTHREADS, 1) void k_gemm() {
    extern __shared__ char smem[];
    const int tid = threadIdx.x;
    const int lane = tid & 31;
    const int wid = tid >> 5;
    const int wm = wid >> 2;       // 0..1
    const int wn = wid & 3;        // 0..3
    const int i0 = blockIdx.y * 128;
    const int j0 = blockIdx.x * 128;
    const uint32_t sb = (uint32_t)__cvta_generic_to_shared(smem);
    int* s_hp = (int*)(smem + SMEM_RED);
    int* s_hn = s_hp + 128;

    if (tid < 128) { s_hp[tid] = 0; s_hn[tid] = 0x7F7FFFFF; }

    float acc[4][4][4];
    #pragma unroll
    for (int a = 0; a < 4; a++)
        #pragma unroll
        for (int b = 0; b < 4; b++)
            #pragma unroll
            for (int c = 0; c < 4; c++)
                acc[a][b][c] = 0.f;

    // ldmatrix per-lane offsets
    const int rA = ((lane >> 3) & 1) * 8 + (lane & 7);
    const int cA = (lane >> 4);            // 0..1  (k-chunk within k16)
    const int rB = ((lane >> 4) << 3) + (lane & 7);
    const int cB = (lane >> 3) & 1;

    issue_stage(sb, i0, j0, 0, tid);
    cp_commit();

    for (int s = 0; s < NSTAGE; s++) {
        if (s < NSTAGE - 1) {
            issue_stage(sb + ((s + 1) & 1) * STAGE_BYTES, i0, j0, s + 1, tid);
            cp_commit();
            cp_wait<1>();
        } else {
            cp_wait<0>();
        }
        __syncthreads();

        const uint32_t st = sb + (s & 1) * STAGE_BYTES;
        const uint32_t Ahi = st, Alo = st + TILE_BYTES;
        const uint32_t Bhi = st + 2 * TILE_BYTES, Blo = st + 3 * TILE_BYTES;

        #pragma unroll
        for (int kk = 0; kk < 2; kk++) {
            uint32_t ahi[4][4], alo[4][4], bhi[2][4], blo[2][4];
            #pragma unroll
            for (int mi = 0; mi < 4; mi++) {
                uint32_t off = (uint32_t)((wm * 64 + mi * 16 + rA) * STRIDE +
                                          (kk * 2 + cA) * 16);
                ldm4(ahi[mi], Ahi + off);
                ldm4(alo[mi], Alo + off);
            }
            #pragma unroll
            for (int p = 0; p < 2; p++) {
                uint32_t off = (uint32_t)((wn * 32 + p * 16 + rB) * STRIDE +
                                          (kk * 2 + cB) * 16);
                ldm4(bhi[p], Bhi + off);
                ldm4(blo[p], Blo + off);
            }
            #pragma unroll
            for (int mi = 0; mi < 4; mi++) {
                #pragma unroll
                for (int ni = 0; ni < 4; ni++) {
                    const int p = ni >> 1, o = (ni & 1) * 2;
                    mma_bf16(acc[mi][ni], ahi[mi], bhi[p][o], bhi[p][o + 1]);
                    mma_bf16(acc[mi][ni], ahi[mi], blo[p][o], blo[p][o + 1]);
                    mma_bf16(acc[mi][ni], alo[mi], bhi[p][o], bhi[p][o + 1]);
                }
            }
        }
        __syncthreads();
    }

    // ---- epilogue: masked hard pos/neg on C fragments ----
    int lj[8], gjs[8];
    float sqj[8];
    #pragma unroll
    for (int idx = 0; idx < 8; idx++) {
        const int ni = idx >> 1, c = idx & 1;
        const int gj = j0 + wn * 32 + ni * 8 + (lane & 3) * 2 + c;
        gjs[idx] = gj;
        lj[idx] = g_lab[gj];
        sqj[idx] = g_sq[gj];
    }

    #pragma unroll
    for (int mi = 0; mi < 4; mi++) {
        #pragma unroll
        for (int h = 0; h < 2; h++) {
            const int rloc = wm * 64 + mi * 16 + h * 8 + (lane >> 2);
            const int gi = i0 + rloc;
            const int li = g_lab[gi];
            const float sqi = g_sq[gi];
            float hp = 0.f, hn = 3.4e38f;
            #pragma unroll
            for (int ni = 0; ni < 4; ni++) {
                #pragma unroll
                for (int c = 0; c < 2; c++) {
                    const int idx = ni * 2 + c;
                    float d2 = fmaf(-2.f, acc[mi][ni][h * 2 + c], sqi + sqj[idx]);
                    if (lj[idx] == li) {
                        if (gjs[idx] != gi) hp = fmaxf(hp, d2);
                    } else {
                        hn = fminf(hn, d2);
                    }
                }
            }
            hp = fmaxf(hp, __shfl_xor_sync(0xFFFFFFFFu, hp, 1));
            hn = fminf(hn, __shfl_xor_sync(0xFFFFFFFFu, hn, 1));
            hp = fmaxf(hp, __shfl_xor_sync(0xFFFFFFFFu, hp, 2));
            hn = fminf(hn, __shfl_xor_sync(0xFFFFFFFFu, hn, 2));
            if ((lane & 3) == 0) {
                atomicMax(&s_hp[rloc], __float_as_int(hp));
                atomicMin(&s_hn[rloc], __float_as_int(hn));
            }
        }
    }
    __syncthreads();
    if (tid < 128) {
        atomicMax(&g_hp_bits[i0 + tid], s_hp[tid]);
        atomicMin(&g_hn_bits[i0 + tid], s_hn[tid]);
    }
}

// ---------------------------------------------------------------------------
// k_final
// ---------------------------------------------------------------------------
__global__ __launch_bounds__(256) void k_final(float* __restrict__ out) {
    const int tid = threadIdx.x;
    float sum = 0.f, cnt = 0.f;
    #pragma unroll
    for (int it = 0; it < B / 256; it++) {
        int i = it * 256 + tid;
        const int c = g_cnt[g_lab[i] & 63];
        if (c >= 2 && c <= B - 1) {
            float hp = sqrtf(fmaxf(__int_as_float(g_hp_bits[i]), 0.f));
            float hn = sqrtf(fmaxf(__int_as_float(g_hn_bits[i]), 0.f));
            float l = hp - hn + MARGIN;
            if (l > 0.f) sum += l;
            cnt += 1.f;
        }
    }
    #pragma unroll
    for (int m = 16; m > 0; m >>= 1) {
        sum += __shfl_xor_sync(0xFFFFFFFFu, sum, m);
        cnt += __shfl_xor_sync(0xFFFFFFFFu, cnt, m);
    }
    __shared__ float ss[8], sc[8];
    if ((tid & 31) == 0) { ss[tid >> 5] = sum; sc[tid >> 5] = cnt; }
    __syncthreads();
    if (tid == 0) {
        float S = 0.f, C = 0.f;
        #pragma unroll
        for (int w = 0; w < 8; w++) { S += ss[w]; C += sc[w]; }
        out[0] = (C > 0.f) ? (S / C) : 0.f;
    }
}

// ---------------------------------------------------------------------------
extern "C" void kernel_launch(void* const* d_in, const int* in_sizes, int n_in,
                              void* d_out, int out_size) {
    const float* E = (const float*)d_in[0];
    const int* labels_raw = (const int*)d_in[1];
    float* out = (float*)d_out;

    static bool attr_set = false;
    if (!attr_set) {
        cudaFuncSetAttribute(k_gemm, cudaFuncAttributeMaxDynamicSharedMemorySize,
                             SMEM_TOTAL);
        attr_set = true;
    }

    k_labels<<<1, 1024>>>(labels_raw);
    k_prep<<<(B * D / 4 + 255) / 256, 256>>>(E);
    {
        dim3 blk(32, 8);
        k_sq<<<(B + 7) / 8, blk>>>(E);
    }
    {
        dim3 grd(B / 128, B / 128);   // 32 x 32
        k_gemm<<<grd, NTHREADS, SMEM_TOTAL>>>();
    }
    k_final<<<1, 256>>>(out);
}

// round 6
// speedup vs baseline: 4.9980x; 1.4494x over previous
#include <cuda_runtime.h>
#include <cuda_bf16.h>
#include <math.h>
#include <stdint.h>

#define B 4096
#define D 256
#define MARGIN 0.3f
#define NTHREADS 256
#define BK 32            // bf16 K elems per stage
#define NSTAGE 8         // D / BK
#define NBUF 3
#define STRIDE 80        // smem row stride bytes (conflict-free for ldmatrix)
#define TILE_BYTES (128 * STRIDE)        // 10240 per matrix
#define STAGE_BYTES (4 * TILE_BYTES)     // Ahi|Alo|Bhi|Blo = 40960
#define SMEM_RED (NBUF * STAGE_BYTES)    // 122880
#define SMEM_TOTAL (SMEM_RED + 2048)
#define NTILE 32                         // B / 128
#define NTRI (NTILE * (NTILE + 1) / 2)   // 528

// ---- device scratch ----
__device__ int   g_hp_bits[B];
__device__ int   g_hn_bits[B];
__device__ float g_sq[B];
__device__ int   g_lab[B];
__device__ int   g_cnt[64];
__device__ __nv_bfloat16 g_Ehi[B * D];
__device__ __nv_bfloat16 g_Elo[B * D];

// ---------------------------------------------------------------------------
// PTX helpers (sm_80+ family-safe)
// ---------------------------------------------------------------------------
__device__ __forceinline__ void cp16(uint32_t s, const void* g) {
    asm volatile("cp.async.cg.shared.global [%0], [%1], 16;" :: "r"(s), "l"(g));
}
__device__ __forceinline__ void cp_commit() {
    asm volatile("cp.async.commit_group;");
}
template <int N>
__device__ __forceinline__ void cp_wait() {
    asm volatile("cp.async.wait_group %0;" :: "n"(N));
}
__device__ __forceinline__ void ldm4(uint32_t* r, uint32_t addr) {
    asm volatile("ldmatrix.sync.aligned.m8n8.x4.shared.b16 {%0,%1,%2,%3}, [%4];"
                 : "=r"(r[0]), "=r"(r[1]), "=r"(r[2]), "=r"(r[3]) : "r"(addr));
}
__device__ __forceinline__ void mma_bf16(float* c, const uint32_t* a,
                                         uint32_t b0, uint32_t b1) {
    asm volatile(
        "mma.sync.aligned.m16n8k16.row.col.f32.bf16.bf16.f32 "
        "{%0,%1,%2,%3}, {%4,%5,%6,%7}, {%8,%9}, {%0,%1,%2,%3};"
        : "+f"(c[0]), "+f"(c[1]), "+f"(c[2]), "+f"(c[3])
        : "r"(a[0]), "r"(a[1]), "r"(a[2]), "r"(a[3]), "r"(b0), "r"(b1));
}

// ---------------------------------------------------------------------------
// k_labels: dtype detect + normalize + histogram + init reductions
// ---------------------------------------------------------------------------
__global__ __launch_bounds__(1024) void k_labels(const int* __restrict__ raw) {
    __shared__ int s_any;
    __shared__ int s_hist[64];
    const int tid = threadIdx.x;
    if (tid == 0) s_any = 0;
    if (tid < 64) s_hist[tid] = 0;
    __syncthreads();
    int local = 0;
    for (int i = tid; i < B; i += 1024)
        if (raw[2 * i + 1] != 0) local = 1;
    if (local) atomicOr(&s_any, 1);
    __syncthreads();
    const bool is_i32 = (s_any != 0);
    for (int i = tid; i < B; i += 1024) {
        int l = is_i32 ? raw[i] : raw[2 * i];
        g_lab[i] = l;
        atomicAdd(&s_hist[l & 63], 1);
        g_hp_bits[i] = 0;
        g_hn_bits[i] = 0x7F7FFFFF;
    }
    __syncthreads();
    if (tid < 64) g_cnt[tid] = s_hist[tid];
}

// ---------------------------------------------------------------------------
// k_prep: fused bf16 hi/lo split + row squared norms. One warp per row.
// ---------------------------------------------------------------------------
__global__ __launch_bounds__(256) void k_prep(const float* __restrict__ E) {
    const int row = blockIdx.x * 8 + (threadIdx.x >> 5);
    const int lane = threadIdx.x & 31;
    if (row >= B) return;
    const float4* e = (const float4*)(E + (size_t)row * D);
    float s = 0.f;
    #pragma unroll
    for (int it = 0; it < 2; it++) {
        int q = it * 32 + lane;            // float4 index within row (0..63)
        float4 v = e[q];
        s += v.x * v.x + v.y * v.y + v.z * v.z + v.w * v.w;
        __nv_bfloat16 h0 = __float2bfloat16(v.x);
        __nv_bfloat16 h1 = __float2bfloat16(v.y);
        __nv_bfloat16 h2 = __float2bfloat16(v.z);
        __nv_bfloat16 h3 = __float2bfloat16(v.w);
        __nv_bfloat162* ph = (__nv_bfloat162*)(g_Ehi + (size_t)row * D + 4 * q);
        __nv_bfloat162* pl = (__nv_bfloat162*)(g_Elo + (size_t)row * D + 4 * q);
        ph[0] = __nv_bfloat162(h0, h1);
        ph[1] = __nv_bfloat162(h2, h3);
        pl[0] = __nv_bfloat162(__float2bfloat16(v.x - __bfloat162float(h0)),
                               __float2bfloat16(v.y - __bfloat162float(h1)));
        pl[1] = __nv_bfloat162(__float2bfloat16(v.z - __bfloat162float(h2)),
                               __float2bfloat16(v.w - __bfloat162float(h3)));
    }
    #pragma unroll
    for (int off = 16; off > 0; off >>= 1)
        s += __shfl_xor_sync(0xFFFFFFFFu, s, off);
    if (lane == 0) g_sq[row] = s;
}

// ---------------------------------------------------------------------------
// k_gemm: triangular-tile HMMA split-3, 3-stage cp.async, dual-side epilogue
// ---------------------------------------------------------------------------
__device__ __forceinline__ void issue_stage(uint32_t sbase, int i0, int j0,
                                            int s, int tid) {
    const int k0 = s * BK;
    #pragma unroll
    for (int m = 0; m < 8; m++) {
        int task = m * NTHREADS + tid;          // 0..2047
        int mat = task >> 9;                    // 0 Ahi, 1 Alo, 2 Bhi, 3 Blo
        int idx = task & 511;
        int row = idx >> 2;
        int q = idx & 3;
        int grow = (mat < 2 ? i0 : j0) + row;
        const __nv_bfloat16* base = (mat & 1) ? g_Elo : g_Ehi;
        const __nv_bfloat16* src = base + (size_t)grow * D + k0 + q * 8;
        uint32_t dst = sbase + mat * TILE_BYTES + row * STRIDE + q * 16;
        cp16(dst, src);
    }
}

__global__ __launch_bounds__(NTHREADS, 1) void k_gemm() {
    extern __shared__ char smem[];
    const int tid = threadIdx.x;
    const int lane = tid & 31;
    const int wid = tid >> 5;
    const int wm = wid >> 2;       // 0..1
    const int wn = wid & 3;        // 0..3

    // triangular decode: blockIdx.x -> (bi, bj) with bi <= bj
    int t = blockIdx.x;
    int bi = 0;
    while (t >= NTILE - bi) { t -= NTILE - bi; bi++; }
    const int bj = bi + t;
    const bool diag = (bi == bj);
    const int i0 = bi * 128;
    const int j0 = bj * 128;

    const uint32_t sb = (uint32_t)__cvta_generic_to_shared(smem);
    int* s_hp = (int*)(smem + SMEM_RED);     // rows (i-side)
    int* s_hn = s_hp + 128;
    int* s_hp2 = s_hn + 128;                 // cols (j-side)
    int* s_hn2 = s_hp2 + 128;

    if (tid < 128) {
        s_hp[tid] = 0;  s_hn[tid] = 0x7F7FFFFF;
        s_hp2[tid] = 0; s_hn2[tid] = 0x7F7FFFFF;
    }

    float acc[4][4][4];
    #pragma unroll
    for (int a = 0; a < 4; a++)
        #pragma unroll
        for (int b = 0; b < 4; b++)
            #pragma unroll
            for (int c = 0; c < 4; c++)
                acc[a][b][c] = 0.f;

    const int rA = ((lane >> 3) & 1) * 8 + (lane & 7);
    const int cA = (lane >> 4);
    const int rB = ((lane >> 4) << 3) + (lane & 7);
    const int cB = (lane >> 3) & 1;

    issue_stage(sb, i0, j0, 0, tid);
    cp_commit();
    issue_stage(sb + STAGE_BYTES, i0, j0, 1, tid);
    cp_commit();

    for (int s = 0; s < NSTAGE; s++) {
        if (s + 2 < NSTAGE) {
            issue_stage(sb + ((s + 2) % NBUF) * STAGE_BYTES, i0, j0, s + 2, tid);
            cp_commit();
            cp_wait<2>();
        } else if (s + 2 == NSTAGE) {
            cp_wait<1>();
        } else {
            cp_wait<0>();
        }
        __syncthreads();

        const uint32_t st = sb + (s % NBUF) * STAGE_BYTES;
        const uint32_t Ahi = st, Alo = st + TILE_BYTES;
        const uint32_t Bhi = st + 2 * TILE_BYTES, Blo = st + 3 * TILE_BYTES;

        #pragma unroll
        for (int kk = 0; kk < 2; kk++) {
            uint32_t ahi[4][4], alo[4][4], bhi[2][4], blo[2][4];
            #pragma unroll
            for (int mi = 0; mi < 4; mi++) {
                uint32_t off = (uint32_t)((wm * 64 + mi * 16 + rA) * STRIDE +
                                          (kk * 2 + cA) * 16);
                ldm4(ahi[mi], Ahi + off);
                ldm4(alo[mi], Alo + off);
            }
            #pragma unroll
            for (int p = 0; p < 2; p++) {
                uint32_t off = (uint32_t)((wn * 32 + p * 16 + rB) * STRIDE +
                                          (kk * 2 + cB) * 16);
                ldm4(bhi[p], Bhi + off);
                ldm4(blo[p], Blo + off);
            }
            #pragma unroll
            for (int mi = 0; mi < 4; mi++) {
                #pragma unroll
                for (int ni = 0; ni < 4; ni++) {
                    const int p = ni >> 1, o = (ni & 1) * 2;
                    mma_bf16(acc[mi][ni], ahi[mi], bhi[p][o], bhi[p][o + 1]);
                    mma_bf16(acc[mi][ni], ahi[mi], blo[p][o], blo[p][o + 1]);
                    mma_bf16(acc[mi][ni], alo[mi], bhi[p][o], bhi[p][o + 1]);
                }
            }
        }
        __syncthreads();
    }

    // ---- epilogue: row-side and (off-diag) column-side hard pos/neg ----
    int lj[8], gjs[8];
    float sqj[8];
    #pragma unroll
    for (int idx = 0; idx < 8; idx++) {
        const int ni = idx >> 1, c = idx & 1;
        const int gj = j0 + wn * 32 + ni * 8 + (lane & 3) * 2 + c;
        gjs[idx] = gj;
        lj[idx] = g_lab[gj];
        sqj[idx] = g_sq[gj];
    }

    float chp[8], chn[8];
    #pragma unroll
    for (int idx = 0; idx < 8; idx++) { chp[idx] = 0.f; chn[idx] = 3.4e38f; }

    #pragma unroll
    for (int mi = 0; mi < 4; mi++) {
        #pragma unroll
        for (int h = 0; h < 2; h++) {
            const int rloc = wm * 64 + mi * 16 + h * 8 + (lane >> 2);
            const int gi = i0 + rloc;
            const int li = g_lab[gi];
            const float sqi = g_sq[gi];
            float hp = 0.f, hn = 3.4e38f;
            #pragma unroll
            for (int ni = 0; ni < 4; ni++) {
                #pragma unroll
                for (int c = 0; c < 2; c++) {
                    const int idx = ni * 2 + c;
                    float d2 = fmaf(-2.f, acc[mi][ni][h * 2 + c], sqi + sqj[idx]);
                    const bool same = (lj[idx] == li);
                    const bool self = (gjs[idx] == gi);
                    if (same) {
                        if (!self) {
                            hp = fmaxf(hp, d2);
                            chp[idx] = fmaxf(chp[idx], d2);
                        }
                    } else {
                        hn = fminf(hn, d2);
                        chn[idx] = fminf(chn[idx], d2);
                    }
                }
            }
            hp = fmaxf(hp, __shfl_xor_sync(0xFFFFFFFFu, hp, 1));
            hn = fminf(hn, __shfl_xor_sync(0xFFFFFFFFu, hn, 1));
            hp = fmaxf(hp, __shfl_xor_sync(0xFFFFFFFFu, hp, 2));
            hn = fminf(hn, __shfl_xor_sync(0xFFFFFFFFu, hn, 2));
            if ((lane & 3) == 0) {
                atomicMax(&s_hp[rloc], __float_as_int(hp));
                atomicMin(&s_hn[rloc], __float_as_int(hn));
            }
        }
    }

    if (!diag) {
        // column-side: reduce over row-direction lanes (4, 8, 16)
        #pragma unroll
        for (int idx = 0; idx < 8; idx++) {
            float vp = chp[idx], vn = chn[idx];
            #pragma unroll
            for (int m = 4; m < 32; m <<= 1) {
                vp = fmaxf(vp, __shfl_xor_sync(0xFFFFFFFFu, vp, m));
                vn = fminf(vn, __shfl_xor_sync(0xFFFFFFFFu, vn, m));
            }
            if ((lane >> 2) == 0) {
                const int ni = idx >> 1, c = idx & 1;
                const int cloc = wn * 32 + ni * 8 + (lane & 3) * 2 + c;
                atomicMax(&s_hp2[cloc], __float_as_int(vp));
                atomicMin(&s_hn2[cloc], __float_as_int(vn));
            }
        }
    }

    __syncthreads();
    if (tid < 128) {
        atomicMax(&g_hp_bits[i0 + tid], s_hp[tid]);
        atomicMin(&g_hn_bits[i0 + tid], s_hn[tid]);
        if (!diag) {
            atomicMax(&g_hp_bits[j0 + tid], s_hp2[tid]);
            atomicMin(&g_hn_bits[j0 + tid], s_hn2[tid]);
        }
    }
}

// ---------------------------------------------------------------------------
// k_final
// ---------------------------------------------------------------------------
__global__ __launch_bounds__(256) void k_final(float* __restrict__ out) {
    const int tid = threadIdx.x;
    float sum = 0.f, cnt = 0.f;
    #pragma unroll
    for (int it = 0; it < B / 256; it++) {
        int i = it * 256 + tid;
        const int c = g_cnt[g_lab[i] & 63];
        if (c >= 2 && c <= B - 1) {
            float hp = sqrtf(fmaxf(__int_as_float(g_hp_bits[i]), 0.f));
            float hn = sqrtf(fmaxf(__int_as_float(g_hn_bits[i]), 0.f));
            float l = hp - hn + MARGIN;
            if (l > 0.f) sum += l;
            cnt += 1.f;
        }
    }
    #pragma unroll
    for (int m = 16; m > 0; m >>= 1) {
        sum += __shfl_xor_sync(0xFFFFFFFFu, sum, m);
        cnt += __shfl_xor_sync(0xFFFFFFFFu, cnt, m);
    }
    __shared__ float ss[8], sc[8];
    if ((tid & 31) == 0) { ss[tid >> 5] = sum; sc[tid >> 5] = cnt; }
    __syncthreads();
    if (tid == 0) {
        float S = 0.f, C = 0.f;
        #pragma unroll
        for (int w = 0; w < 8; w++) { S += ss[w]; C += sc[w]; }
        out[0] = (C > 0.f) ? (S / C) : 0.f;
    }
}

// ---------------------------------------------------------------------------
extern "C" void kernel_launch(void* const* d_in, const int* in_sizes, int n_in,
                              void* d_out, int out_size) {
    const float* E = (const float*)d_in[0];
    const int* labels_raw = (const int*)d_in[1];
    float* out = (float*)d_out;

    static bool attr_set = false;
    if (!attr_set) {
        cudaFuncSetAttribute(k_gemm, cudaFuncAttributeMaxDynamicSharedMemorySize,
                             SMEM_TOTAL);
        attr_set = true;
    }

    k_labels<<<1, 1024>>>(labels_raw);
    k_prep<<<B / 8, 256>>>(E);
    k_gemm<<<NTRI, NTHREADS, SMEM_TOTAL>>>();
    k_final<<<1, 256>>>(out);
}

// round 7
// speedup vs baseline: 6.2500x; 1.2505x over previous
#include <cuda_runtime.h>
#include <cuda_bf16.h>
#include <math.h>
#include <stdint.h>

#define B 4096
#define D 256
#define MARGIN 0.3f
#define NTHREADS 512
#define BK 32            // bf16 K elems per stage
#define NSTAGE 8         // D / BK
#define NBUF 3
#define STRIDE 80        // smem row stride bytes (conflict-free for ldmatrix)
#define TILE_BYTES (128 * STRIDE)        // 10240 per matrix
#define STAGE_BYTES (4 * TILE_BYTES)     // Ahi|Alo|Bhi|Blo = 40960
#define SMEM_RED (NBUF * STAGE_BYTES)    // 122880
#define SMEM_TOTAL (SMEM_RED + 2048)
#define NTILE 32                         // B / 128
#define NTRI (NTILE * (NTILE + 1) / 2)   // 528

// ---- device scratch ----
__device__ int   g_hp_bits[B];
__device__ int   g_hn_bits[B];
__device__ float g_sq[B];
__device__ int   g_lab[B];
__device__ int   g_cnt[64];
__device__ float g_sum;
__device__ float g_vcnt;
__device__ __nv_bfloat16 g_Ehi[B * D];
__device__ __nv_bfloat16 g_Elo[B * D];

// ---------------------------------------------------------------------------
// PTX helpers (sm_80+ family-safe)
// ---------------------------------------------------------------------------
__device__ __forceinline__ void cp16(uint32_t s, const void* g) {
    asm volatile("cp.async.cg.shared.global [%0], [%1], 16;" :: "r"(s), "l"(g));
}
__device__ __forceinline__ void cp_commit() {
    asm volatile("cp.async.commit_group;");
}
template <int N>
__device__ __forceinline__ void cp_wait() {
    asm volatile("cp.async.wait_group %0;" :: "n"(N));
}
__device__ __forceinline__ void ldm4(uint32_t* r, uint32_t addr) {
    asm volatile("ldmatrix.sync.aligned.m8n8.x4.shared.b16 {%0,%1,%2,%3}, [%4];"
                 : "=r"(r[0]), "=r"(r[1]), "=r"(r[2]), "=r"(r[3]) : "r"(addr));
}
__device__ __forceinline__ void mma_bf16(float* c, const uint32_t* a,
                                         uint32_t b0, uint32_t b1) {
    asm volatile(
        "mma.sync.aligned.m16n8k16.row.col.f32.bf16.bf16.f32 "
        "{%0,%1,%2,%3}, {%4,%5,%6,%7}, {%8,%9}, {%0,%1,%2,%3};"
        : "+f"(c[0]), "+f"(c[1]), "+f"(c[2]), "+f"(c[3])
        : "r"(a[0]), "r"(a[1]), "r"(a[2]), "r"(a[3]), "r"(b0), "r"(b1));
}

// ---------------------------------------------------------------------------
// k_labels: dtype detect + normalize + histogram + init reductions/accums
// ---------------------------------------------------------------------------
__global__ __launch_bounds__(1024) void k_labels(const int* __restrict__ raw) {
    __shared__ int s_any;
    __shared__ int s_hist[64];
    const int tid = threadIdx.x;
    if (tid == 0) { s_any = 0; g_sum = 0.f; g_vcnt = 0.f; }
    if (tid < 64) s_hist[tid] = 0;
    __syncthreads();
    int local = 0;
    for (int i = tid; i < B; i += 1024)
        if (raw[2 * i + 1] != 0) local = 1;
    if (local) atomicOr(&s_any, 1);
    __syncthreads();
    const bool is_i32 = (s_any != 0);
    for (int i = tid; i < B; i += 1024) {
        int l = is_i32 ? raw[i] : raw[2 * i];
        g_lab[i] = l;
        atomicAdd(&s_hist[l & 63], 1);
        g_hp_bits[i] = 0;
        g_hn_bits[i] = 0x7F7FFFFF;
    }
    __syncthreads();
    if (tid < 64) g_cnt[tid] = s_hist[tid];
}

// ---------------------------------------------------------------------------
// k_prep: fused bf16 hi/lo split + row squared norms. One warp per row.
// ---------------------------------------------------------------------------
__global__ __launch_bounds__(256) void k_prep(const float* __restrict__ E) {
    const int row = blockIdx.x * 8 + (threadIdx.x >> 5);
    const int lane = threadIdx.x & 31;
    if (row >= B) return;
    const float4* e = (const float4*)(E + (size_t)row * D);
    float s = 0.f;
    #pragma unroll
    for (int it = 0; it < 2; it++) {
        int q = it * 32 + lane;
        float4 v = e[q];
        s += v.x * v.x + v.y * v.y + v.z * v.z + v.w * v.w;
        __nv_bfloat16 h0 = __float2bfloat16(v.x);
        __nv_bfloat16 h1 = __float2bfloat16(v.y);
        __nv_bfloat16 h2 = __float2bfloat16(v.z);
        __nv_bfloat16 h3 = __float2bfloat16(v.w);
        __nv_bfloat162* ph = (__nv_bfloat162*)(g_Ehi + (size_t)row * D + 4 * q);
        __nv_bfloat162* pl = (__nv_bfloat162*)(g_Elo + (size_t)row * D + 4 * q);
        ph[0] = __nv_bfloat162(h0, h1);
        ph[1] = __nv_bfloat162(h2, h3);
        pl[0] = __nv_bfloat162(__float2bfloat16(v.x - __bfloat162float(h0)),
                               __float2bfloat16(v.y - __bfloat162float(h1)));
        pl[1] = __nv_bfloat162(__float2bfloat16(v.z - __bfloat162float(h2)),
                               __float2bfloat16(v.w - __bfloat162float(h3)));
    }
    #pragma unroll
    for (int off = 16; off > 0; off >>= 1)
        s += __shfl_xor_sync(0xFFFFFFFFu, s, off);
    if (lane == 0) g_sq[row] = s;
}

// ---------------------------------------------------------------------------
// k_gemm: triangular tiles, 512 threads / 16 warps, warp tile 32x32,
//         HMMA split-3, 3-stage cp.async, dual-side epilogue
// ---------------------------------------------------------------------------
__device__ __forceinline__ void issue_stage(uint32_t sbase, int i0, int j0,
                                            int s, int tid) {
    const int k0 = s * BK;
    #pragma unroll
    for (int m = 0; m < 4; m++) {
        int task = m * NTHREADS + tid;          // 0..2047
        int mat = task >> 9;                    // 0 Ahi, 1 Alo, 2 Bhi, 3 Blo
        int idx = task & 511;
        int row = idx >> 2;
        int q = idx & 3;
        int grow = (mat < 2 ? i0 : j0) + row;
        const __nv_bfloat16* base = (mat & 1) ? g_Elo : g_Ehi;
        const __nv_bfloat16* src = base + (size_t)grow * D + k0 + q * 8;
        uint32_t dst = sbase + mat * TILE_BYTES + row * STRIDE + q * 16;
        cp16(dst, src);
    }
}

__global__ __launch_bounds__(NTHREADS, 1) void k_gemm() {
    extern __shared__ char smem[];
    const int tid = threadIdx.x;
    const int lane = tid & 31;
    const int wid = tid >> 5;
    const int wm = wid >> 2;       // 0..3
    const int wn = wid & 3;        // 0..3

    // triangular decode: blockIdx.x -> (bi, bj) with bi <= bj
    int t = blockIdx.x;
    int bi = 0;
    while (t >= NTILE - bi) { t -= NTILE - bi; bi++; }
    const int bj = bi + t;
    const bool diag = (bi == bj);
    const int i0 = bi * 128;
    const int j0 = bj * 128;

    const uint32_t sb = (uint32_t)__cvta_generic_to_shared(smem);
    int* s_hp = (int*)(smem + SMEM_RED);     // rows (i-side)
    int* s_hn = s_hp + 128;
    int* s_hp2 = s_hn + 128;                 // cols (j-side)
    int* s_hn2 = s_hp2 + 128;

    if (tid < 128) {
        s_hp[tid] = 0;  s_hn[tid] = 0x7F7FFFFF;
        s_hp2[tid] = 0; s_hn2[tid] = 0x7F7FFFFF;
    }

    float acc[2][4][4];
    #pragma unroll
    for (int a = 0; a < 2; a++)
        #pragma unroll
        for (int b = 0; b < 4; b++)
            #pragma unroll
            for (int c = 0; c < 4; c++)
                acc[a][b][c] = 0.f;

    const int rA = ((lane >> 3) & 1) * 8 + (lane & 7);
    const int cA = (lane >> 4);
    const int rB = ((lane >> 4) << 3) + (lane & 7);
    const int cB = (lane >> 3) & 1;

    issue_stage(sb, i0, j0, 0, tid);
    cp_commit();
    issue_stage(sb + STAGE_BYTES, i0, j0, 1, tid);
    cp_commit();

    for (int s = 0; s < NSTAGE; s++) {
        if (s + 2 < NSTAGE) {
            issue_stage(sb + ((s + 2) % NBUF) * STAGE_BYTES, i0, j0, s + 2, tid);
            cp_commit();
            cp_wait<2>();
        } else if (s + 2 == NSTAGE) {
            cp_wait<1>();
        } else {
            cp_wait<0>();
        }
        __syncthreads();

        const uint32_t st = sb + (s % NBUF) * STAGE_BYTES;
        const uint32_t Ahi = st, Alo = st + TILE_BYTES;
        const uint32_t Bhi = st + 2 * TILE_BYTES, Blo = st + 3 * TILE_BYTES;

        #pragma unroll
        for (int kk = 0; kk < 2; kk++) {
            uint32_t ahi[2][4], alo[2][4], bhi[2][4], blo[2][4];
            #pragma unroll
            for (int mi = 0; mi < 2; mi++) {
                uint32_t off = (uint32_t)((wm * 32 + mi * 16 + rA) * STRIDE +
                                          (kk * 2 + cA) * 16);
                ldm4(ahi[mi], Ahi + off);
                ldm4(alo[mi], Alo + off);
            }
            #pragma unroll
            for (int p = 0; p < 2; p++) {
                uint32_t off = (uint32_t)((wn * 32 + p * 16 + rB) * STRIDE +
                                          (kk * 2 + cB) * 16);
                ldm4(bhi[p], Bhi + off);
                ldm4(blo[p], Blo + off);
            }
            #pragma unroll
            for (int mi = 0; mi < 2; mi++) {
                #pragma unroll
                for (int ni = 0; ni < 4; ni++) {
                    const int p = ni >> 1, o = (ni & 1) * 2;
                    mma_bf16(acc[mi][ni], ahi[mi], bhi[p][o], bhi[p][o + 1]);
                    mma_bf16(acc[mi][ni], ahi[mi], blo[p][o], blo[p][o + 1]);
                    mma_bf16(acc[mi][ni], alo[mi], bhi[p][o], bhi[p][o + 1]);
                }
            }
        }
        __syncthreads();
    }

    // ---- epilogue: row-side and (off-diag) column-side hard pos/neg ----
    int lj[8], gjs[8];
    float sqj[8];
    #pragma unroll
    for (int idx = 0; idx < 8; idx++) {
        const int ni = idx >> 1, c = idx & 1;
        const int gj = j0 + wn * 32 + ni * 8 + (lane & 3) * 2 + c;
        gjs[idx] = gj;
        lj[idx] = g_lab[gj];
        sqj[idx] = g_sq[gj];
    }

    float chp[8], chn[8];
    #pragma unroll
    for (int idx = 0; idx < 8; idx++) { chp[idx] = 0.f; chn[idx] = 3.4e38f; }

    #pragma unroll
    for (int mi = 0; mi < 2; mi++) {
        #pragma unroll
        for (int h = 0; h < 2; h++) {
            const int rloc = wm * 32 + mi * 16 + h * 8 + (lane >> 2);
            const int gi = i0 + rloc;
            const int li = g_lab[gi];
            const float sqi = g_sq[gi];
            float hp = 0.f, hn = 3.4e38f;
            #pragma unroll
            for (int ni = 0; ni < 4; ni++) {
                #pragma unroll
                for (int c = 0; c < 2; c++) {
                    const int idx = ni * 2 + c;
                    float d2 = fmaf(-2.f, acc[mi][ni][h * 2 + c], sqi + sqj[idx]);
                    const bool same = (lj[idx] == li);
                    const bool self = (gjs[idx] == gi);
                    if (same) {
                        if (!self) {
                            hp = fmaxf(hp, d2);
                            chp[idx] = fmaxf(chp[idx], d2);
                        }
                    } else {
                        hn = fminf(hn, d2);
                        chn[idx] = fminf(chn[idx], d2);
                    }
                }
            }
            hp = fmaxf(hp, __shfl_xor_sync(0xFFFFFFFFu, hp, 1));
            hn = fminf(hn, __shfl_xor_sync(0xFFFFFFFFu, hn, 1));
            hp = fmaxf(hp, __shfl_xor_sync(0xFFFFFFFFu, hp, 2));
            hn = fminf(hn, __shfl_xor_sync(0xFFFFFFFFu, hn, 2));
            if ((lane & 3) == 0) {
                atomicMax(&s_hp[rloc], __float_as_int(hp));
                atomicMin(&s_hn[rloc], __float_as_int(hn));
            }
        }
    }

    if (!diag) {
        #pragma unroll
        for (int idx = 0; idx < 8; idx++) {
            float vp = chp[idx], vn = chn[idx];
            #pragma unroll
            for (int m = 4; m < 32; m <<= 1) {
                vp = fmaxf(vp, __shfl_xor_sync(0xFFFFFFFFu, vp, m));
                vn = fminf(vn, __shfl_xor_sync(0xFFFFFFFFu, vn, m));
            }
            if ((lane >> 2) == 0) {
                const int ni = idx >> 1, c = idx & 1;
                const int cloc = wn * 32 + ni * 8 + (lane & 3) * 2 + c;
                atomicMax(&s_hp2[cloc], __float_as_int(vp));
                atomicMin(&s_hn2[cloc], __float_as_int(vn));
            }
        }
    }

    __syncthreads();
    if (tid < 128) {
        atomicMax(&g_hp_bits[i0 + tid], s_hp[tid]);
        atomicMin(&g_hn_bits[i0 + tid], s_hn[tid]);
        if (!diag) {
            atomicMax(&g_hp_bits[j0 + tid], s_hp2[tid]);
            atomicMin(&g_hn_bits[j0 + tid], s_hn2[tid]);
        }
    }
}

// ---------------------------------------------------------------------------
// k_final: 16 blocks of partial sums -> global atomics
// ---------------------------------------------------------------------------
__global__ __launch_bounds__(256) void k_final() {
    const int i = blockIdx.x * 256 + threadIdx.x;
    const int tid = threadIdx.x;
    float sum = 0.f, cnt = 0.f;
    const int c = g_cnt[g_lab[i] & 63];
    if (c >= 2 && c <= B - 1) {
        float hp = sqrtf(fmaxf(__int_as_float(g_hp_bits[i]), 0.f));
        float hn = sqrtf(fmaxf(__int_as_float(g_hn_bits[i]), 0.f));
        float l = hp - hn + MARGIN;
        if (l > 0.f) sum = l;
        cnt = 1.f;
    }
    #pragma unroll
    for (int m = 16; m > 0; m >>= 1) {
        sum += __shfl_xor_sync(0xFFFFFFFFu, sum, m);
        cnt += __shfl_xor_sync(0xFFFFFFFFu, cnt, m);
    }
    __shared__ float ss[8], sc[8];
    if ((tid & 31) == 0) { ss[tid >> 5] = sum; sc[tid >> 5] = cnt; }
    __syncthreads();
    if (tid == 0) {
        float S = 0.f, C = 0.f;
        #pragma unroll
        for (int w = 0; w < 8; w++) { S += ss[w]; C += sc[w]; }
        atomicAdd(&g_sum, S);
        atomicAdd(&g_vcnt, C);
    }
}

__global__ void k_div(float* __restrict__ out) {
    if (threadIdx.x == 0) {
        float c = g_vcnt;
        out[0] = (c > 0.f) ? (g_sum / c) : 0.f;
    }
}

// ---------------------------------------------------------------------------
extern "C" void kernel_launch(void* const* d_in, const int* in_sizes, int n_in,
                              void* d_out, int out_size) {
    const float* E = (const float*)d_in[0];
    const int* labels_raw = (const int*)d_in[1];
    float* out = (float*)d_out;

    static bool attr_set = false;
    if (!attr_set) {
        cudaFuncSetAttribute(k_gemm, cudaFuncAttributeMaxDynamicSharedMemorySize,
                             SMEM_TOTAL);
        attr_set = true;
    }

    k_labels<<<1, 1024>>>(labels_raw);
    k_prep<<<B / 8, 256>>>(E);
    k_gemm<<<NTRI, NTHREADS, SMEM_TOTAL>>>();
    k_final<<<B / 256, 256>>>();
    k_div<<<1, 32>>>(out);
}

// round 8
// speedup vs baseline: 6.4484x; 1.0317x over previous
#include <cuda_runtime.h>
#include <cuda_bf16.h>
#include <math.h>
#include <stdint.h>

#define B 4096
#define D 256
#define MARGIN 0.3f
#define NTHREADS 512
#define BK 64            // bf16 K elems per stage
#define NSTAGE 4         // D / BK
#define NBUF 3
#define STRIDE 144       // 128B data + 16B pad (9 mod 32 -> conflict-free ldmatrix)
#define TILE_BYTES (128 * STRIDE)        // 18432 per matrix
#define STAGE_BYTES (4 * TILE_BYTES)     // Ahi|Alo|Bhi|Blo = 73728
#define SMEM_RED (NBUF * STAGE_BYTES)    // 221184
#define SMEM_TOTAL (SMEM_RED + 2048)     // 223232 (< 227KB cap)
#define NTILE 32                         // B / 128
#define NTRI (NTILE * (NTILE + 1) / 2)   // 528

// ---- device scratch ----
__device__ int   g_hp_bits[B];
__device__ int   g_hn_bits[B];
__device__ float g_sq[B];
__device__ int   g_lab[B];
__device__ int   g_cnt[64];
__device__ float g_sum;
__device__ float g_vcnt;
__device__ unsigned int g_done;
__device__ __nv_bfloat16 g_Ehi[B * D];
__device__ __nv_bfloat16 g_Elo[B * D];

// ---------------------------------------------------------------------------
// PTX helpers (sm_80+ family-safe)
// ---------------------------------------------------------------------------
__device__ __forceinline__ void cp16(uint32_t s, const void* g) {
    asm volatile("cp.async.cg.shared.global [%0], [%1], 16;" :: "r"(s), "l"(g));
}
__device__ __forceinline__ void cp_commit() {
    asm volatile("cp.async.commit_group;");
}
template <int N>
__device__ __forceinline__ void cp_wait() {
    asm volatile("cp.async.wait_group %0;" :: "n"(N));
}
__device__ __forceinline__ void ldm4(uint32_t* r, uint32_t addr) {
    asm volatile("ldmatrix.sync.aligned.m8n8.x4.shared.b16 {%0,%1,%2,%3}, [%4];"
                 : "=r"(r[0]), "=r"(r[1]), "=r"(r[2]), "=r"(r[3]) : "r"(addr));
}
__device__ __forceinline__ void mma_bf16(float* c, const uint32_t* a,
                                         uint32_t b0, uint32_t b1) {
    asm volatile(
        "mma.sync.aligned.m16n8k16.row.col.f32.bf16.bf16.f32 "
        "{%0,%1,%2,%3}, {%4,%5,%6,%7}, {%8,%9}, {%0,%1,%2,%3};"
        : "+f"(c[0]), "+f"(c[1]), "+f"(c[2]), "+f"(c[3])
        : "r"(a[0]), "r"(a[1]), "r"(a[2]), "r"(a[3]), "r"(b0), "r"(b1));
}

// ---------------------------------------------------------------------------
// k_prep: blocks 0..511 = bf16 hi/lo split + row norms (one warp per row);
//         block 512 = label normalize + histogram + reduction init.
// ---------------------------------------------------------------------------
__global__ __launch_bounds__(256) void k_prep(const float* __restrict__ E,
                                              const int* __restrict__ raw) {
    if (blockIdx.x == 512) {
        __shared__ int s_any;
        __shared__ int s_hist[64];
        const int tid = threadIdx.x;
        if (tid == 0) { s_any = 0; g_sum = 0.f; g_vcnt = 0.f; g_done = 0u; }
        if (tid < 64) s_hist[tid] = 0;
        __syncthreads();
        int local = 0;
        for (int i = tid; i < B; i += 256)
            if (raw[2 * i + 1] != 0) local = 1;
        if (local) atomicOr(&s_any, 1);
        __syncthreads();
        const bool is_i32 = (s_any != 0);
        for (int i = tid; i < B; i += 256) {
            int l = is_i32 ? raw[i] : raw[2 * i];
            g_lab[i] = l;
            atomicAdd(&s_hist[l & 63], 1);
            g_hp_bits[i] = 0;
            g_hn_bits[i] = 0x7F7FFFFF;
        }
        __syncthreads();
        if (tid < 64) g_cnt[tid] = s_hist[tid];
        return;
    }

    const int row = blockIdx.x * 8 + (threadIdx.x >> 5);
    const int lane = threadIdx.x & 31;
    const float4* e = (const float4*)(E + (size_t)row * D);
    float s = 0.f;
    #pragma unroll
    for (int it = 0; it < 2; it++) {
        int q = it * 32 + lane;
        float4 v = e[q];
        s += v.x * v.x + v.y * v.y + v.z * v.z + v.w * v.w;
        __nv_bfloat16 h0 = __float2bfloat16(v.x);
        __nv_bfloat16 h1 = __float2bfloat16(v.y);
        __nv_bfloat16 h2 = __float2bfloat16(v.z);
        __nv_bfloat16 h3 = __float2bfloat16(v.w);
        __nv_bfloat162* ph = (__nv_bfloat162*)(g_Ehi + (size_t)row * D + 4 * q);
        __nv_bfloat162* pl = (__nv_bfloat162*)(g_Elo + (size_t)row * D + 4 * q);
        ph[0] = __nv_bfloat162(h0, h1);
        ph[1] = __nv_bfloat162(h2, h3);
        pl[0] = __nv_bfloat162(__float2bfloat16(v.x - __bfloat162float(h0)),
                               __float2bfloat16(v.y - __bfloat162float(h1)));
        pl[1] = __nv_bfloat162(__float2bfloat16(v.z - __bfloat162float(h2)),
                               __float2bfloat16(v.w - __bfloat162float(h3)));
    }
    #pragma unroll
    for (int off = 16; off > 0; off >>= 1)
        s += __shfl_xor_sync(0xFFFFFFFFu, s, off);
    if (lane == 0) g_sq[row] = s;
}

// ---------------------------------------------------------------------------
// k_gemm: triangular tiles, 16 warps, warp tile 32x32, HMMA split-3,
//         3-buffer cp.async with ONE sync per stage, dual-side epilogue
// ---------------------------------------------------------------------------
__device__ __forceinline__ void issue_stage(uint32_t sbase, int i0, int j0,
                                            int s, int tid) {
    const int k0 = s * BK;
    #pragma unroll
    for (int m = 0; m < 8; m++) {
        int task = m * NTHREADS + tid;          // 0..4095
        int mat = task >> 10;                   // 0 Ahi, 1 Alo, 2 Bhi, 3 Blo
        int idx = task & 1023;
        int row = idx >> 3;
        int q = idx & 7;
        int grow = (mat < 2 ? i0 : j0) + row;
        const __nv_bfloat16* base = (mat & 1) ? g_Elo : g_Ehi;
        const __nv_bfloat16* src = base + (size_t)grow * D + k0 + q * 8;
        uint32_t dst = sbase + mat * TILE_BYTES + row * STRIDE + q * 16;
        cp16(dst, src);
    }
}

__global__ __launch_bounds__(NTHREADS, 1) void k_gemm() {
    extern __shared__ char smem[];
    const int tid = threadIdx.x;
    const int lane = tid & 31;
    const int wid = tid >> 5;
    const int wm = wid >> 2;       // 0..3
    const int wn = wid & 3;        // 0..3

    int t = blockIdx.x;
    int bi = 0;
    while (t >= NTILE - bi) { t -= NTILE - bi; bi++; }
    const int bj = bi + t;
    const bool diag = (bi == bj);
    const int i0 = bi * 128;
    const int j0 = bj * 128;

    const uint32_t sb = (uint32_t)__cvta_generic_to_shared(smem);
    int* s_hp = (int*)(smem + SMEM_RED);
    int* s_hn = s_hp + 128;
    int* s_hp2 = s_hn + 128;
    int* s_hn2 = s_hp2 + 128;

    if (tid < 128) {
        s_hp[tid] = 0;  s_hn[tid] = 0x7F7FFFFF;
        s_hp2[tid] = 0; s_hn2[tid] = 0x7F7FFFFF;
    }

    float acc[2][4][4];
    #pragma unroll
    for (int a = 0; a < 2; a++)
        #pragma unroll
        for (int b = 0; b < 4; b++)
            #pragma unroll
            for (int c = 0; c < 4; c++)
                acc[a][b][c] = 0.f;

    const int rA = ((lane >> 3) & 1) * 8 + (lane & 7);
    const int cA = (lane >> 4);
    const int rB = ((lane >> 4) << 3) + (lane & 7);
    const int cB = (lane >> 3) & 1;

    issue_stage(sb, i0, j0, 0, tid);
    cp_commit();
    issue_stage(sb + STAGE_BYTES, i0, j0, 1, tid);
    cp_commit();

    #pragma unroll
    for (int s = 0; s < NSTAGE; s++) {
        if (s < NSTAGE - 1) cp_wait<1>(); else cp_wait<0>();
        __syncthreads();
        if (s + 2 < NSTAGE) {
            issue_stage(sb + ((s + 2) % NBUF) * STAGE_BYTES, i0, j0, s + 2, tid);
            cp_commit();
        }

        const uint32_t st = sb + (s % NBUF) * STAGE_BYTES;
        const uint32_t Ahi = st, Alo = st + TILE_BYTES;
        const uint32_t Bhi = st + 2 * TILE_BYTES, Blo = st + 3 * TILE_BYTES;

        #pragma unroll
        for (int kk = 0; kk < 4; kk++) {
            uint32_t ahi[2][4], alo[2][4], bhi[2][4], blo[2][4];
            #pragma unroll
            for (int mi = 0; mi < 2; mi++) {
                uint32_t off = (uint32_t)((wm * 32 + mi * 16 + rA) * STRIDE +
                                          (kk * 2 + cA) * 16);
                ldm4(ahi[mi], Ahi + off);
                ldm4(alo[mi], Alo + off);
            }
            #pragma unroll
            for (int p = 0; p < 2; p++) {
                uint32_t off = (uint32_t)((wn * 32 + p * 16 + rB) * STRIDE +
                                          (kk * 2 + cB) * 16);
                ldm4(bhi[p], Bhi + off);
                ldm4(blo[p], Blo + off);
            }
            #pragma unroll
            for (int mi = 0; mi < 2; mi++) {
                #pragma unroll
                for (int ni = 0; ni < 4; ni++) {
                    const int p = ni >> 1, o = (ni & 1) * 2;
                    mma_bf16(acc[mi][ni], ahi[mi], bhi[p][o], bhi[p][o + 1]);
                    mma_bf16(acc[mi][ni], ahi[mi], blo[p][o], blo[p][o + 1]);
                    mma_bf16(acc[mi][ni], alo[mi], bhi[p][o], bhi[p][o + 1]);
                }
            }
        }
    }
    __syncthreads();

    // ---- epilogue ----
    int lj[8], gjs[8];
    float sqj[8];
    #pragma unroll
    for (int idx = 0; idx < 8; idx++) {
        const int ni = idx >> 1, c = idx & 1;
        const int gj = j0 + wn * 32 + ni * 8 + (lane & 3) * 2 + c;
        gjs[idx] = gj;
        lj[idx] = g_lab[gj];
        sqj[idx] = g_sq[gj];
    }

    float chp[8], chn[8];
    #pragma unroll
    for (int idx = 0; idx < 8; idx++) { chp[idx] = 0.f; chn[idx] = 3.4e38f; }

    #pragma unroll
    for (int mi = 0; mi < 2; mi++) {
        #pragma unroll
        for (int h = 0; h < 2; h++) {
            const int rloc = wm * 32 + mi * 16 + h * 8 + (lane >> 2);
            const int gi = i0 + rloc;
            const int li = g_lab[gi];
            const float sqi = g_sq[gi];
            float hp = 0.f, hn = 3.4e38f;
            #pragma unroll
            for (int ni = 0; ni < 4; ni++) {
                #pragma unroll
                for (int c = 0; c < 2; c++) {
                    const int idx = ni * 2 + c;
                    float d2 = fmaf(-2.f, acc[mi][ni][h * 2 + c], sqi + sqj[idx]);
                    const bool same = (lj[idx] == li);
                    const bool self = (gjs[idx] == gi);
                    if (same) {
                        if (!self) {
                            hp = fmaxf(hp, d2);
                            chp[idx] = fmaxf(chp[idx], d2);
                        }
                    } else {
                        hn = fminf(hn, d2);
                        chn[idx] = fminf(chn[idx], d2);
                    }
                }
            }
            hp = fmaxf(hp, __shfl_xor_sync(0xFFFFFFFFu, hp, 1));
            hn = fminf(hn, __shfl_xor_sync(0xFFFFFFFFu, hn, 1));
            hp = fmaxf(hp, __shfl_xor_sync(0xFFFFFFFFu, hp, 2));
            hn = fminf(hn, __shfl_xor_sync(0xFFFFFFFFu, hn, 2));
            if ((lane & 3) == 0) {
                atomicMax(&s_hp[rloc], __float_as_int(hp));
                atomicMin(&s_hn[rloc], __float_as_int(hn));
            }
        }
    }

    if (!diag) {
        #pragma unroll
        for (int idx = 0; idx < 8; idx++) {
            float vp = chp[idx], vn = chn[idx];
            #pragma unroll
            for (int m = 4; m < 32; m <<= 1) {
                vp = fmaxf(vp, __shfl_xor_sync(0xFFFFFFFFu, vp, m));
                vn = fminf(vn, __shfl_xor_sync(0xFFFFFFFFu, vn, m));
            }
            if ((lane >> 2) == 0) {
                const int ni = idx >> 1, c = idx & 1;
                const int cloc = wn * 32 + ni * 8 + (lane & 3) * 2 + c;
                atomicMax(&s_hp2[cloc], __float_as_int(vp));
                atomicMin(&s_hn2[cloc], __float_as_int(vn));
            }
        }
    }

    __syncthreads();
    if (tid < 128) {
        atomicMax(&g_hp_bits[i0 + tid], s_hp[tid]);
        atomicMin(&g_hn_bits[i0 + tid], s_hn[tid]);
        if (!diag) {
            atomicMax(&g_hp_bits[j0 + tid], s_hp2[tid]);
            atomicMin(&g_hn_bits[j0 + tid], s_hn2[tid]);
        }
    }
}

// ---------------------------------------------------------------------------
// k_final: 16 partial blocks -> atomics; last block writes out.
// ---------------------------------------------------------------------------
__global__ __launch_bounds__(256) void k_final(float* __restrict__ out) {
    const int i = blockIdx.x * 256 + threadIdx.x;
    const int tid = threadIdx.x;
    float sum = 0.f, cnt = 0.f;
    const int c = g_cnt[g_lab[i] & 63];
    if (c >= 2 && c <= B - 1) {
        float hp = sqrtf(fmaxf(__int_as_float(g_hp_bits[i]), 0.f));
        float hn = sqrtf(fmaxf(__int_as_float(g_hn_bits[i]), 0.f));
        float l = hp - hn + MARGIN;
        if (l > 0.f) sum = l;
        cnt = 1.f;
    }
    #pragma unroll
    for (int m = 16; m > 0; m >>= 1) {
        sum += __shfl_xor_sync(0xFFFFFFFFu, sum, m);
        cnt += __shfl_xor_sync(0xFFFFFFFFu, cnt, m);
    }
    __shared__ float ss[8], sc[8];
    __shared__ bool is_last;
    if ((tid & 31) == 0) { ss[tid >> 5] = sum; sc[tid >> 5] = cnt; }
    __syncthreads();
    if (tid == 0) {
        float S = 0.f, C = 0.f;
        #pragma unroll
        for (int w = 0; w < 8; w++) { S += ss[w]; C += sc[w]; }
        atomicAdd(&g_sum, S);
        atomicAdd(&g_vcnt, C);
        __threadfence();
        unsigned int n = atomicAdd(&g_done, 1u);
        is_last = (n == gridDim.x - 1);
    }
    __syncthreads();
    if (is_last && tid == 0) {
        float cfin = *((volatile float*)&g_vcnt);
        float sfin = *((volatile float*)&g_sum);
        out[0] = (cfin > 0.f) ? (sfin / cfin) : 0.f;
    }
}

// ---------------------------------------------------------------------------
extern "C" void kernel_launch(void* const* d_in, const int* in_sizes, int n_in,
                              void* d_out, int out_size) {
    const float* E = (const float*)d_in[0];
    const int* labels_raw = (const int*)d_in[1];
    float* out = (float*)d_out;

    static bool attr_set = false;
    if (!attr_set) {
        cudaFuncSetAttribute(k_gemm, cudaFuncAttributeMaxDynamicSharedMemorySize,
                             SMEM_TOTAL);
        attr_set = true;
    }

    k_prep<<<513, 256>>>(E, labels_raw);
    k_gemm<<<NTRI, NTHREADS, SMEM_TOTAL>>>();
    k_final<<<B / 256, 256>>>(out);
}